// round 6
// baseline (speedup 1.0000x reference)
#include <cuda_runtime.h>
#include <cuda_fp16.h>
#include <cstdint>

// Problem constants
#define BATCH   32
#define NPATCH  576
#define MTOT    (BATCH * NPATCH)   // 18432
#define KDIM    768                // 3*16*16
#define EMBED   768

// ---------------------------------------------------------------------------
// Scratch (device globals: allocation-free rule). Single fp16 A and B.
// ---------------------------------------------------------------------------
__device__ __align__(16) __half g_A[(size_t)MTOT * KDIM];
__device__ __align__(16) __half g_B[(size_t)EMBED * KDIM];

// ---------------------------------------------------------------------------
// Helpers (base sm_103-target-legal only)
// ---------------------------------------------------------------------------
__device__ __forceinline__ uint32_t smem_u32(const void* p) {
    uint32_t a;
    asm("{ .reg .u64 t; cvta.to.shared.u64 t, %1; cvt.u32.u64 %0, t; }" : "=r"(a) : "l"(p));
    return a;
}

__device__ __forceinline__ void cp16(uint32_t dst, const void* src) {
    asm volatile("cp.async.cg.shared.global [%0], [%1], 16;\n" :: "r"(dst), "l"(src));
}
#define CP_COMMIT() asm volatile("cp.async.commit_group;\n" ::: "memory")
#define CP_WAIT(n)  asm volatile("cp.async.wait_group %0;\n" :: "n"(n) : "memory")

#define LDSM_X4(r, addr)                                                        \
    asm volatile("ldmatrix.sync.aligned.m8n8.x4.shared.b16 {%0,%1,%2,%3}, [%4];" \
        : "=r"((r)[0]), "=r"((r)[1]), "=r"((r)[2]), "=r"((r)[3]) : "r"(addr))

#define MMA_F16(d, a, b0, b1)                                                   \
    asm volatile("mma.sync.aligned.m16n8k16.row.col.f32.f16.f16.f32 "           \
        "{%0,%1,%2,%3}, {%4,%5,%6,%7}, {%8,%9}, {%0,%1,%2,%3};"                 \
        : "+f"((d)[0]), "+f"((d)[1]), "+f"((d)[2]), "+f"((d)[3])                \
        : "r"((a)[0]), "r"((a)[1]), "r"((a)[2]), "r"((a)[3]), "r"(b0), "r"(b1))

// ---------------------------------------------------------------------------
// Kernel 1 (fused): blocks [0,2304): gather patches -> fp16 A [18432, 768]
//                   blocks [2304,3456): proj_w -> fp16 B [768, 768]
// ---------------------------------------------------------------------------
template <int S>
__device__ __forceinline__ void convert_pairs(const float (&e)[20], unsigned (&uh)[8]) {
#pragma unroll
    for (int k = 0; k < 8; k++) {
        __half2 hp = __halves2half2(__float2half_rn(e[S + 2 * k]),
                                    __float2half_rn(e[S + 2 * k + 1]));
        uh[k] = *reinterpret_cast<unsigned*>(&hp);
    }
}

__global__ __launch_bounds__(256) void prep_kernel(const float* __restrict__ x,
                                                   const int* __restrict__ h_idx,
                                                   const int* __restrict__ w_idx,
                                                   const float* __restrict__ pw) {
    if (blockIdx.x >= 2304) {
        int i = (blockIdx.x - 2304) * 256 + threadIdx.x;
        float2 v = reinterpret_cast<const float2*>(pw)[i];
        __half2 hp = __halves2half2(__float2half_rn(v.x), __float2half_rn(v.y));
        reinterpret_cast<unsigned*>(g_B)[i] = *reinterpret_cast<unsigned*>(&hp);
        return;
    }
    int warp = (blockIdx.x << 3) + (threadIdx.x >> 5);   // 0..18431
    int lane = threadIdx.x & 31;
    int b = warp / NPATCH;
    int h = h_idx[warp];
    int w = w_idx[warp];
    int s  = w & 3;
    int a0 = w & ~3;
    const float* xb = x + (size_t)b * (3 * 384 * 384);
    __half* oh = g_A + (size_t)warp * KDIM;

#pragma unroll
    for (int pass = 0; pass < 2; ++pass) {
        int rr = (pass << 5) + lane;          // row task 0..47  (c*16 + ph)
        if (rr < 48) {
            int c = rr >> 4, ph = rr & 15;
            const float4* src = reinterpret_cast<const float4*>(
                xb + (size_t)(c * 384 + h + ph) * 384 + a0);
            float4 f0 = src[0], f1 = src[1], f2 = src[2], f3 = src[3];
            float4 f4 = make_float4(0.f, 0.f, 0.f, 0.f);
            if (s != 0) f4 = src[4];
            float e[20] = {f0.x, f0.y, f0.z, f0.w, f1.x, f1.y, f1.z, f1.w,
                           f2.x, f2.y, f2.z, f2.w, f3.x, f3.y, f3.z, f3.w,
                           f4.x, f4.y, f4.z, f4.w};
            unsigned uh[8];
            switch (s) {
                case 0:  convert_pairs<0>(e, uh); break;
                case 1:  convert_pairs<1>(e, uh); break;
                case 2:  convert_pairs<2>(e, uh); break;
                default: convert_pairs<3>(e, uh); break;
            }
            uint4* dh = reinterpret_cast<uint4*>(oh + rr * 16);
            dh[0] = make_uint4(uh[0], uh[1], uh[2], uh[3]);
            dh[1] = make_uint4(uh[4], uh[5], uh[6], uh[7]);
        }
    }
}

// ---------------------------------------------------------------------------
// Kernel 2: GEMM. BM=128, BN=256, BK=32. 8 warps = 2m x 4n, warp tile 64x64.
// X/Y register fragment double-buffer + 4-stage cp.async ring, unrolled k-loop.
// Crossbar bytes/FLOP cut 33% vs 32x64 warp tiles -> tensor pipe unthrottled.
// ---------------------------------------------------------------------------
static constexpr int ROW_B  = 80;
static constexpr int MAT_A  = 128 * ROW_B;          // 10240
static constexpr int MAT_B  = 256 * ROW_B;          // 20480
static constexpr int OFF_A  = 0;
static constexpr int OFF_B  = MAT_A;
static constexpr int STAGE_BYTES = MAT_A + MAT_B;   // 30720
static constexpr int N_STAGE = 4;
static constexpr int GEMM_SMEM = N_STAGE * STAGE_BYTES;  // 122880
static constexpr int KTILES = 24;

__device__ __forceinline__ void stage(uint32_t sbuf, int kt, int mbase, int nbase, int tid) {
    const __half* ga = g_A + (size_t)mbase * KDIM + kt * 32;
    const __half* gb = g_B + (size_t)nbase * KDIM + kt * 32;
#pragma unroll
    for (int i = 0; i < 2; i++) {                 // A: 128 rows x 4 segs = 512 units
        int idx = tid + i * 256;
        int row = idx >> 2, seg = idx & 3;
        cp16(sbuf + OFF_A + (uint32_t)(row * ROW_B + seg * 16),
             ga + (size_t)row * KDIM + seg * 8);
    }
#pragma unroll
    for (int i = 0; i < 4; i++) {                 // B: 256 rows x 4 segs = 1024 units
        int idx = tid + i * 256;
        int row = idx >> 2, seg = idx & 3;
        cp16(sbuf + OFF_B + (uint32_t)(row * ROW_B + seg * 16),
             gb + (size_t)row * KDIM + seg * 8);
    }
}

__device__ __forceinline__ void load_frags(uint32_t (&fa)[4][4], uint32_t (&fb)[4][4],
                                           uint32_t a_base, uint32_t b_base) {
#pragma unroll
    for (int mf = 0; mf < 4; mf++) LDSM_X4(fa[mf], a_base + mf * 16 * ROW_B);
#pragma unroll
    for (int nb = 0; nb < 4; nb++) LDSM_X4(fb[nb], b_base + nb * 16 * ROW_B);
}

__device__ __forceinline__ void mma_all(float (&acc)[4][8][4],
                                        uint32_t (&fa)[4][4], uint32_t (&fb)[4][4]) {
#pragma unroll
    for (int mf = 0; mf < 4; mf++)
#pragma unroll
        for (int nf = 0; nf < 8; nf++) {
            int nb = nf >> 1, sel = nf & 1;
            MMA_F16(acc[mf][nf], fa[mf], fb[nb][sel], fb[nb][2 + sel]);
        }
}

__global__ __launch_bounds__(256, 1) void gemm_kernel(const float* __restrict__ proj_b,
                                                      float* __restrict__ out) {
    extern __shared__ char smem[];
    uint32_t sb = smem_u32(smem);
    int tid = threadIdx.x;
    int lane = tid & 31, wid = tid >> 5;
    int wm = wid & 1, wn = wid >> 1;              // 2m x 4n warps, 64x64 tiles
    int nbase = blockIdx.x * 256;                 // x fastest: 3 CTAs share one A tile
    int mbase = blockIdx.y * 128;

    float acc[4][8][4];
#pragma unroll
    for (int a = 0; a < 4; a++)
#pragma unroll
        for (int b = 0; b < 8; b++)
#pragma unroll
            for (int c = 0; c < 4; c++) acc[a][b][c] = 0.f;

    int r15 = lane & 15;
    uint32_t khalf = (uint32_t)((lane >> 4) * 16);
    uint32_t a0 = sb + OFF_A + (uint32_t)((wm * 64 + r15) * ROW_B) + khalf;
    uint32_t b0 = sb + OFF_B + (uint32_t)((wn * 64 + r15) * ROW_B) + khalf;

    uint32_t xa[4][4], xb[4][4];   // fragments, half-tile "X" (ks0)
    uint32_t ya[4][4], yb[4][4];   // fragments, half-tile "Y" (ks1)

    // Prologue: fill 3 ring slots, make slot 0 visible, preload X = ks0 of kt0.
    stage(sb, 0, mbase, nbase, tid);                   CP_COMMIT();
    stage(sb + STAGE_BYTES, 1, mbase, nbase, tid);     CP_COMMIT();
    stage(sb + 2 * STAGE_BYTES, 2, mbase, nbase, tid); CP_COMMIT();
    CP_WAIT(2);
    __syncthreads();
    load_frags(xa, xb, a0, b0);

#pragma unroll
    for (int kt = 0; kt < KTILES; kt++) {
        const uint32_t slot = (uint32_t)((kt % N_STAGE) * STAGE_BYTES);
        // 1) LDSM Y <- ks1 of tile kt (same slot; visible since prior barrier)
        load_frags(ya, yb, a0 + slot + 32, b0 + slot + 32);
        // 2) 32 MMAs on X — LDSM latency hidden under these
        mma_all(acc, xa, xb);
        // 3) refill ring slot (kt+3)%4 with tile kt+3
        if (kt + 3 < KTILES) {
            stage(sb + (uint32_t)(((kt + 3) % N_STAGE) * STAGE_BYTES), kt + 3, mbase, nbase, tid);
            CP_COMMIT();
        }
        if (kt < KTILES - 1) {
            if (kt <= KTILES - 4)      { CP_WAIT(2); }
            else if (kt == KTILES - 3) { CP_WAIT(1); }
            else                       { CP_WAIT(0); }
            __syncthreads();
            const uint32_t nslot = (uint32_t)(((kt + 1) % N_STAGE) * STAGE_BYTES);
            load_frags(xa, xb, a0 + nslot, b0 + nslot);
        }
        // 4) 32 MMAs on Y
        mma_all(acc, ya, yb);
    }

    // Epilogue: acc + bias -> out
#pragma unroll
    for (int mf = 0; mf < 4; mf++) {
#pragma unroll
        for (int nf = 0; nf < 8; nf++) {
            int row = mbase + wm * 64 + mf * 16 + (lane >> 2);
            int col = nbase + wn * 64 + nf * 8 + (lane & 3) * 2;
            float2 bv = *reinterpret_cast<const float2*>(proj_b + col);
            float2 o0 = make_float2(acc[mf][nf][0] + bv.x, acc[mf][nf][1] + bv.y);
            float2 o1 = make_float2(acc[mf][nf][2] + bv.x, acc[mf][nf][3] + bv.y);
            *reinterpret_cast<float2*>(out + (size_t)row * EMBED + col) = o0;
            *reinterpret_cast<float2*>(out + (size_t)(row + 8) * EMBED + col) = o1;
        }
    }
}

// ---------------------------------------------------------------------------
// kernel_launch
// ---------------------------------------------------------------------------
extern "C" void kernel_launch(void* const* d_in, const int* in_sizes, int n_in,
                              void* d_out, int out_size) {
    const float* x      = (const float*)d_in[0];
    const int*   h_idx  = (const int*)d_in[1];
    const int*   w_idx  = (const int*)d_in[2];
    const float* proj_w = (const float*)d_in[3];
    const float* proj_b = (const float*)d_in[4];
    float* out = (float*)d_out;

    prep_kernel<<<3456, 256>>>(x, h_idx, w_idx, proj_w);  // gather + B prep fused

    cudaFuncSetAttribute(gemm_kernel, cudaFuncAttributeMaxDynamicSharedMemorySize, GEMM_SMEM);
    gemm_kernel<<<dim3(3, 144), 256, GEMM_SMEM>>>(proj_b, out);
}

// round 7
// speedup vs baseline: 1.1287x; 1.1287x over previous
#include <cuda_runtime.h>
#include <cuda_fp16.h>
#include <cstdint>

// Problem constants
#define BATCH   32
#define NPATCH  576
#define MTOT    (BATCH * NPATCH)   // 18432
#define KDIM    768                // 3*16*16
#define EMBED   768

// ---------------------------------------------------------------------------
// Scratch (device globals: allocation-free rule). Single fp16 A and B.
// ---------------------------------------------------------------------------
__device__ __align__(16) __half g_A[(size_t)MTOT * KDIM];
__device__ __align__(16) __half g_B[(size_t)EMBED * KDIM];

// ---------------------------------------------------------------------------
// Helpers (base sm_103-target-legal only)
// ---------------------------------------------------------------------------
__device__ __forceinline__ uint32_t smem_u32(const void* p) {
    uint32_t a;
    asm("{ .reg .u64 t; cvta.to.shared.u64 t, %1; cvt.u32.u64 %0, t; }" : "=r"(a) : "l"(p));
    return a;
}

__device__ __forceinline__ void cp16(uint32_t dst, const void* src) {
    asm volatile("cp.async.cg.shared.global [%0], [%1], 16;\n" :: "r"(dst), "l"(src));
}
#define CP_COMMIT() asm volatile("cp.async.commit_group;\n" ::: "memory")
#define CP_WAIT(n)  asm volatile("cp.async.wait_group %0;\n" :: "n"(n) : "memory")

#define LDSM_X4(r, addr)                                                        \
    asm volatile("ldmatrix.sync.aligned.m8n8.x4.shared.b16 {%0,%1,%2,%3}, [%4];" \
        : "=r"((r)[0]), "=r"((r)[1]), "=r"((r)[2]), "=r"((r)[3]) : "r"(addr))

#define MMA_F16(d, a, b0, b1)                                                   \
    asm volatile("mma.sync.aligned.m16n8k16.row.col.f32.f16.f16.f32 "           \
        "{%0,%1,%2,%3}, {%4,%5,%6,%7}, {%8,%9}, {%0,%1,%2,%3};"                 \
        : "+f"((d)[0]), "+f"((d)[1]), "+f"((d)[2]), "+f"((d)[3])                \
        : "r"((a)[0]), "r"((a)[1]), "r"((a)[2]), "r"((a)[3]), "r"(b0), "r"(b1))

// ---------------------------------------------------------------------------
// Kernel 1 (fused): blocks [0,2304): gather patches -> fp16 A [18432, 768]
//                   blocks [2304,3456): proj_w -> fp16 B [768, 768]
// ---------------------------------------------------------------------------
template <int S>
__device__ __forceinline__ void convert_pairs(const float (&e)[20], unsigned (&uh)[8]) {
#pragma unroll
    for (int k = 0; k < 8; k++) {
        __half2 hp = __halves2half2(__float2half_rn(e[S + 2 * k]),
                                    __float2half_rn(e[S + 2 * k + 1]));
        uh[k] = *reinterpret_cast<unsigned*>(&hp);
    }
}

__global__ __launch_bounds__(256) void prep_kernel(const float* __restrict__ x,
                                                   const int* __restrict__ h_idx,
                                                   const int* __restrict__ w_idx,
                                                   const float* __restrict__ pw) {
    if (blockIdx.x >= 2304) {
        int i = (blockIdx.x - 2304) * 256 + threadIdx.x;
        float2 v = reinterpret_cast<const float2*>(pw)[i];
        __half2 hp = __halves2half2(__float2half_rn(v.x), __float2half_rn(v.y));
        reinterpret_cast<unsigned*>(g_B)[i] = *reinterpret_cast<unsigned*>(&hp);
        return;
    }
    int warp = (blockIdx.x << 3) + (threadIdx.x >> 5);   // 0..18431
    int lane = threadIdx.x & 31;
    int b = warp / NPATCH;
    int h = h_idx[warp];
    int w = w_idx[warp];
    int s  = w & 3;
    int a0 = w & ~3;
    const float* xb = x + (size_t)b * (3 * 384 * 384);
    __half* oh = g_A + (size_t)warp * KDIM;

#pragma unroll
    for (int pass = 0; pass < 2; ++pass) {
        int rr = (pass << 5) + lane;          // row task 0..47  (c*16 + ph)
        if (rr < 48) {
            int c = rr >> 4, ph = rr & 15;
            const float4* src = reinterpret_cast<const float4*>(
                xb + (size_t)(c * 384 + h + ph) * 384 + a0);
            float4 f0 = src[0], f1 = src[1], f2 = src[2], f3 = src[3];
            float4 f4 = make_float4(0.f, 0.f, 0.f, 0.f);
            if (s != 0) f4 = src[4];
            float e[20] = {f0.x, f0.y, f0.z, f0.w, f1.x, f1.y, f1.z, f1.w,
                           f2.x, f2.y, f2.z, f2.w, f3.x, f3.y, f3.z, f3.w,
                           f4.x, f4.y, f4.z, f4.w};
            unsigned uh[8];
            switch (s) {
                case 0:  convert_pairs<0>(e, uh); break;
                case 1:  convert_pairs<1>(e, uh); break;
                case 2:  convert_pairs<2>(e, uh); break;
                default: convert_pairs<3>(e, uh); break;
            }
            uint4* dh = reinterpret_cast<uint4*>(oh + rr * 16);
            dh[0] = make_uint4(uh[0], uh[1], uh[2], uh[3]);
            dh[1] = make_uint4(uh[4], uh[5], uh[6], uh[7]);
        }
    }
}

// ---------------------------------------------------------------------------
// Kernel 2: GEMM. BM=128, BN=128, BK=32, 8 warps (4m x 2n, 32x64 warp tiles),
// 2 CTAs/SM. Phase-staggered warps: per SMSP, one warp MMA-bursts while its
// mate LDSM-bursts, so crossbar and tensor pipes overlap instead of alternate.
// 5-stage cp.async ring, depth-4 prefetch, fully unrolled k-loop.
// ---------------------------------------------------------------------------
static constexpr int ROW_B     = 80;
static constexpr int MAT_BYTES = 128 * ROW_B;       // 10240
static constexpr int OFF_A = 0;
static constexpr int OFF_B = MAT_BYTES;
static constexpr int STAGE_BYTES = 2 * MAT_BYTES;   // 20480
static constexpr int N_STAGE = 5;
static constexpr int GEMM_SMEM = N_STAGE * STAGE_BYTES;  // 102400 (x2 CTAs = 200KB/SM)
static constexpr int KTILES = 24;

__device__ __forceinline__ void stage(uint32_t sbuf, int kt, int mbase, int nbase, int tid) {
    const __half* ga = g_A + (size_t)mbase * KDIM + kt * 32;
    const __half* gb = g_B + (size_t)nbase * KDIM + kt * 32;
#pragma unroll
    for (int i = 0; i < 2; i++) {
        int idx = tid + i * 256;              // 0..511 = 128 rows x 4 segs
        int row = idx >> 2, seg = idx & 3;
        uint32_t off = (uint32_t)(row * ROW_B + seg * 16);
        size_t g = (size_t)row * KDIM + seg * 8;
        cp16(sbuf + OFF_A + off, ga + g);
        cp16(sbuf + OFF_B + off, gb + g);
    }
}

__device__ __forceinline__ void load_frags(uint32_t (&fa)[2][4], uint32_t (&fb)[4][4],
                                           uint32_t a_base, uint32_t b_base) {
    LDSM_X4(fa[0], a_base);
    LDSM_X4(fa[1], a_base + 16 * ROW_B);
#pragma unroll
    for (int nb = 0; nb < 4; nb++) LDSM_X4(fb[nb], b_base + nb * 16 * ROW_B);
}

__device__ __forceinline__ void mma_all(float (&acc)[2][8][4],
                                        uint32_t (&fa)[2][4], uint32_t (&fb)[4][4]) {
#pragma unroll
    for (int mf = 0; mf < 2; mf++)
#pragma unroll
        for (int nf = 0; nf < 8; nf++) {
            int nb = nf >> 1, sel = nf & 1;
            MMA_F16(acc[mf][nf], fa[mf], fb[nb][sel], fb[nb][2 + sel]);
        }
}

__global__ __launch_bounds__(256, 2) void gemm_kernel(const float* __restrict__ proj_b,
                                                      float* __restrict__ out) {
    extern __shared__ char smem[];
    uint32_t sb = smem_u32(smem);
    int tid = threadIdx.x;
    int lane = tid & 31, wid = tid >> 5;
    int wm = wid & 3, wn = wid >> 2;
    bool ph0 = ((wid >> 2) & 1) == 0;  // warps 0-3 phase0, 4-7 phase1 (opposite SMSP mates)
    int nbase = blockIdx.x * 128;      // x fastest: 6 CTAs share one A tile in L2
    int mbase = blockIdx.y * 128;

    float acc[2][8][4];
#pragma unroll
    for (int a = 0; a < 2; a++)
#pragma unroll
        for (int b = 0; b < 8; b++)
#pragma unroll
            for (int c = 0; c < 4; c++) acc[a][b][c] = 0.f;

    int r15 = lane & 15;
    uint32_t khalf = (uint32_t)((lane >> 4) * 16);
    uint32_t a0 = sb + OFF_A + (uint32_t)((wm * 32 + r15) * ROW_B) + khalf;
    uint32_t b0 = sb + OFF_B + (uint32_t)((wn * 64 + r15) * ROW_B) + khalf;

    uint32_t xa[2][4], xb[4][4];   // fragments, half-tile "X" (ks0)
    uint32_t ya[2][4], yb[4][4];   // fragments, half-tile "Y" (ks1)

    // Prologue: fill 4 of 5 ring slots, ensure tile 0 complete, preload X(kt0).
    stage(sb, 0, mbase, nbase, tid);                   CP_COMMIT();
    stage(sb + STAGE_BYTES, 1, mbase, nbase, tid);     CP_COMMIT();
    stage(sb + 2 * STAGE_BYTES, 2, mbase, nbase, tid); CP_COMMIT();
    stage(sb + 3 * STAGE_BYTES, 3, mbase, nbase, tid); CP_COMMIT();
    CP_WAIT(3);
    __syncthreads();
    load_frags(xa, xb, a0, b0);

#pragma unroll
    for (int kt = 0; kt < KTILES; kt++) {
        const uint32_t slot = (uint32_t)((kt % N_STAGE) * STAGE_BYTES);
        // Staggered: phase0 loads Y then MMAs X; phase1 MMAs X then loads Y.
        if (ph0) {
            load_frags(ya, yb, a0 + slot + 32, b0 + slot + 32);
            mma_all(acc, xa, xb);
        } else {
            mma_all(acc, xa, xb);
            load_frags(ya, yb, a0 + slot + 32, b0 + slot + 32);
        }
        // Refill ring slot (kt+4)%5 (its last reader synced at iter kt-1's barrier).
        if (kt + 4 < KTILES) {
            stage(sb + (uint32_t)(((kt + 4) % N_STAGE) * STAGE_BYTES), kt + 4, mbase, nbase, tid);
            CP_COMMIT();
        }
        if (kt < KTILES - 1) {
            // Need tile kt+1 complete for the post-barrier X load.
            if (kt + 4 < KTILES)       { CP_WAIT(3); }
            else if (kt + 4 == KTILES) { CP_WAIT(2); }
            else if (kt + 4 == KTILES + 1) { CP_WAIT(1); }
            else                       { CP_WAIT(0); }
            __syncthreads();
            const uint32_t nslot = (uint32_t)(((kt + 1) % N_STAGE) * STAGE_BYTES);
            if (ph0) {
                load_frags(xa, xb, a0 + nslot, b0 + nslot);
                mma_all(acc, ya, yb);
            } else {
                mma_all(acc, ya, yb);
                load_frags(xa, xb, a0 + nslot, b0 + nslot);
            }
        } else {
            mma_all(acc, ya, yb);
        }
    }

    // Epilogue: acc + bias -> out
#pragma unroll
    for (int mf = 0; mf < 2; mf++) {
#pragma unroll
        for (int nf = 0; nf < 8; nf++) {
            int row = mbase + wm * 32 + mf * 16 + (lane >> 2);
            int col = nbase + wn * 64 + nf * 8 + (lane & 3) * 2;
            float2 bv = *reinterpret_cast<const float2*>(proj_b + col);
            float2 o0 = make_float2(acc[mf][nf][0] + bv.x, acc[mf][nf][1] + bv.y);
            float2 o1 = make_float2(acc[mf][nf][2] + bv.x, acc[mf][nf][3] + bv.y);
            *reinterpret_cast<float2*>(out + (size_t)row * EMBED + col) = o0;
            *reinterpret_cast<float2*>(out + (size_t)(row + 8) * EMBED + col) = o1;
        }
    }
}

// ---------------------------------------------------------------------------
// kernel_launch
// ---------------------------------------------------------------------------
extern "C" void kernel_launch(void* const* d_in, const int* in_sizes, int n_in,
                              void* d_out, int out_size) {
    const float* x      = (const float*)d_in[0];
    const int*   h_idx  = (const int*)d_in[1];
    const int*   w_idx  = (const int*)d_in[2];
    const float* proj_w = (const float*)d_in[3];
    const float* proj_b = (const float*)d_in[4];
    float* out = (float*)d_out;

    prep_kernel<<<3456, 256>>>(x, h_idx, w_idx, proj_w);  // gather + B prep fused

    cudaFuncSetAttribute(gemm_kernel, cudaFuncAttributeMaxDynamicSharedMemorySize, GEMM_SMEM);
    gemm_kernel<<<dim3(6, 144), 256, GEMM_SMEM>>>(proj_b, out);
}